// round 7
// baseline (speedup 1.0000x reference)
#include <cuda_runtime.h>
#include <cuda_bf16.h>
#include <mma.h>
#include <cstdint>

using namespace nvcuda;

#define SD 512
#define NB 512
#define SCALE 0.044194173824159216f

#define BM 128
#define BN 256
#define BK 64
#define LDT 72      // bf16 smem tile stride (144B rows: odd 16B multiple, LDSM conflict-free)
#define LDB2 264    // k2 V-tile stride (528B rows)
#define LDC 132     // fp32 staging stride
#define K1_SMEM (BM * LDC * 4)                 // 67584 (tiles 55296 alias)
#define K2_SMEM (128*LDT*2 + 64*LDB2*2 + 2048) // 18432 + 33792 + 2048 = 54272

// ---- scratch (device globals) ----
__device__ __nv_bfloat16 g_E[(size_t)NB * SD * SD];
__device__ float g_partZ[NB][4][SD];
__device__ float g_Zinv[NB][SD];

__device__ __forceinline__ uint2 pack4(float4 v) {
    __nv_bfloat162 a = __float22bfloat162_rn(make_float2(v.x, v.y));
    __nv_bfloat162 b = __float22bfloat162_rn(make_float2(v.z, v.w));
    uint2 u;
    u.x = *(uint32_t*)&a;
    u.y = *(uint32_t*)&b;
    return u;
}

// ---------------------------------------------------------------------------
// k1: S = Q K^T, E = exp(scale*S) -> gmem, column partial sums.
// CTA tile 128x256, 512 threads = 16 warps (4 row x 4 col), warp tile 32x64.
// grid (8, 512): blockIdx.x = it*2 + nh  (nh = which 256-col half).
// dyn smem: As[128][72] @0 (18432B), Bs[256][72] @18432 (36864B);
//           aliased post-loop by Cs fp32 [128][132] (67584B).
// ---------------------------------------------------------------------------
__global__ void __launch_bounds__(512) k1_qk(const float* __restrict__ Q,
                                             const float* __restrict__ Km)
{
    extern __shared__ char sm[];
    __nv_bfloat16* As = (__nv_bfloat16*)sm;
    __nv_bfloat16* Bs = (__nv_bfloat16*)(sm + 128 * LDT * 2);
    float* Cs = (float*)sm;
    __shared__ float zs[512];

    const int batch = blockIdx.y;
    const int it = blockIdx.x >> 1;
    const int nh = blockIdx.x & 1;
    const float* Qb = Q  + ((size_t)batch * SD + it * BM) * SD;
    const float* Kb = Km + ((size_t)batch * SD + nh * BN) * SD;

    const int t = threadIdx.x, wid = t >> 5;
    const int wr = wid & 3;    // row group (32 rows)
    const int wc = wid >> 2;   // col group (64 cols of 256)

    wmma::fragment<wmma::accumulator, 16, 16, 16, float> acc[2][4];
#pragma unroll
    for (int a = 0; a < 2; a++)
#pragma unroll
        for (int b = 0; b < 4; b++) wmma::fill_fragment(acc[a][b], 0.0f);

    const int lr = t >> 4;            // 0..31
    const int lq = (t & 15) * 4;      // 0..60

#pragma unroll 1
    for (int kk = 0; kk < SD; kk += BK) {
#pragma unroll
        for (int p = 0; p < 4; p++) {
            const int row = lr + p * 32;
            float4 qa = *(const float4*)(Qb + (size_t)row * SD + kk + lq);
            *(uint2*)(As + row * LDT + lq) = pack4(qa);
        }
#pragma unroll
        for (int p = 0; p < 8; p++) {
            const int row = lr + p * 32;
            float4 ka = *(const float4*)(Kb + (size_t)row * SD + kk + lq);
            *(uint2*)(Bs + row * LDT + lq) = pack4(ka);
        }
        __syncthreads();
#pragma unroll
        for (int ks = 0; ks < BK; ks += 16) {
            wmma::fragment<wmma::matrix_a, 16, 16, 16, __nv_bfloat16, wmma::row_major> af[2];
            wmma::fragment<wmma::matrix_b, 16, 16, 16, __nv_bfloat16, wmma::col_major> bf[4];
#pragma unroll
            for (int a = 0; a < 2; a++)
                wmma::load_matrix_sync(af[a], As + (wr * 32 + a * 16) * LDT + ks, LDT);
#pragma unroll
            for (int b = 0; b < 4; b++)
                wmma::load_matrix_sync(bf[b], Bs + (wc * 64 + b * 16) * LDT + ks, LDT);
#pragma unroll
            for (int a = 0; a < 2; a++)
#pragma unroll
                for (int b = 0; b < 4; b++)
                    wmma::mma_sync(acc[a][b], af[a], bf[b], acc[a][b]);
        }
        __syncthreads();
    }

    // exp in registers
#pragma unroll
    for (int a = 0; a < 2; a++)
#pragma unroll
        for (int b = 0; b < 4; b++)
#pragma unroll
            for (int e = 0; e < acc[a][b].num_elements; e++)
                acc[a][b].x[e] = __expf(acc[a][b].x[e] * SCALE);

    // two epilogue passes of 128 cols each through fp32 staging
    __nv_bfloat16* Eb = g_E + ((size_t)batch * SD + it * BM) * SD + nh * BN;
#pragma unroll 1
    for (int ch = 0; ch < 2; ch++) {
        if ((wc >> 1) == ch) {
#pragma unroll
            for (int a = 0; a < 2; a++)
#pragma unroll
                for (int b = 0; b < 4; b++)
                    wmma::store_matrix_sync(
                        Cs + (wr * 32 + a * 16) * LDC + (wc & 1) * 64 + b * 16,
                        acc[a][b], LDC, wmma::mem_row_major);
        }
        __syncthreads();

        // deterministic column sums: 4 threads per column, fixed order
        {
            const int col = t & 127, q = t >> 7;
            float z = 0.f;
#pragma unroll 8
            for (int r = q * 32; r < q * 32 + 32; r++)
                z += Cs[r * LDC + col];
            zs[t] = z;
        }
        __syncthreads();
        if (t < 128)
            g_partZ[batch][it][nh * BN + ch * 128 + t] =
                zs[t] + zs[t + 128] + zs[t + 256] + zs[t + 384];

        // pack E bf16 coalesced: 4 threads per row, 32 cols each
        {
            const int row = t >> 2, c0 = (t & 3) * 32;
            const float* src = Cs + row * LDC + c0;
            __nv_bfloat16* dst = Eb + (size_t)row * SD + ch * 128 + c0;
#pragma unroll
            for (int i = 0; i < 4; i++) {
                uint2 lo = pack4(*(const float4*)(src + i * 8));
                uint2 hi = pack4(*(const float4*)(src + i * 8 + 4));
                uint4 o; o.x = lo.x; o.y = lo.y; o.z = hi.x; o.w = hi.y;
                *(uint4*)(dst + i * 8) = o;
            }
        }
        __syncthreads();
    }
}

// ---------------------------------------------------------------------------
// k_zred: Z = fixed-order sum of 4 it-partials; store 1/Z
// ---------------------------------------------------------------------------
__global__ void __launch_bounds__(512) k_zred()
{
    const int b = blockIdx.x, c = threadIdx.x;
    float z = g_partZ[b][0][c] + g_partZ[b][1][c] + g_partZ[b][2][c] + g_partZ[b][3][c];
    g_Zinv[b][c] = 1.0f / z;
}

// ---------------------------------------------------------------------------
// k2: out = E @ (diag(1/Z) V). CTA tile 128x256, 512 threads, warp 32x64.
// grid (8, 512): blockIdx.x = it*2 + jh. Direct gmem accumulator stores.
// dyn smem: As(E)[128][72] @0, Bs(V)[64][264] @18432, zs[512] @52224.
// ---------------------------------------------------------------------------
__global__ void __launch_bounds__(512) k2_pv(const float* __restrict__ V,
                                             float* __restrict__ O)
{
    extern __shared__ char sm[];
    __nv_bfloat16* As = (__nv_bfloat16*)sm;
    __nv_bfloat16* Bs = (__nv_bfloat16*)(sm + 128 * LDT * 2);
    float* zs = (float*)(sm + 128 * LDT * 2 + 64 * LDB2 * 2);

    const int batch = blockIdx.y;
    const int it = blockIdx.x >> 1;
    const int jh = blockIdx.x & 1;
    const __nv_bfloat16* Eb = g_E + ((size_t)batch * SD + it * BM) * SD;
    const float* Vb = V + (size_t)batch * SD * SD + jh * BN;

    const int t = threadIdx.x, wid = t >> 5;
    const int wr = wid & 3, wc = wid >> 2;

    zs[t] = g_Zinv[batch][t];

    wmma::fragment<wmma::accumulator, 16, 16, 16, float> acc[2][4];
#pragma unroll
    for (int a = 0; a < 2; a++)
#pragma unroll
        for (int b = 0; b < 4; b++) wmma::fill_fragment(acc[a][b], 0.0f);
    __syncthreads();   // zs visible

    const int er = t >> 3;            // 0..63
    const int ec = (t & 7) * 8;       // 0..56
    const int vj = (t & 7) * 4;       // 0..28

#pragma unroll 1
    for (int kk = 0; kk < SD; kk += BK) {
        // E tile: 128 rows x 64 bf16
        *(uint4*)(As + er * LDT + ec) =
            *(const uint4*)(Eb + (size_t)er * SD + kk + ec);
        *(uint4*)(As + (er + 64) * LDT + ec) =
            *(const uint4*)(Eb + (size_t)(er + 64) * SD + kk + ec);
        // V tile: 64 k-rows x 256 j fp32, scaled by zinv[k] -> bf16
        {
            const int k = er;
            const float zi = zs[kk + k];
            const float* vrow = Vb + (size_t)(kk + k) * SD;
#pragma unroll
            for (int p = 0; p < 8; p++) {
                float4 v = *(const float4*)(vrow + vj + p * 32);
                v.x *= zi; v.y *= zi; v.z *= zi; v.w *= zi;
                *(uint2*)(Bs + k * LDB2 + vj + p * 32) = pack4(v);
            }
        }
        __syncthreads();
#pragma unroll
        for (int ks = 0; ks < BK; ks += 16) {
            wmma::fragment<wmma::matrix_a, 16, 16, 16, __nv_bfloat16, wmma::row_major> af[2];
            wmma::fragment<wmma::matrix_b, 16, 16, 16, __nv_bfloat16, wmma::row_major> bf[4];
#pragma unroll
            for (int a = 0; a < 2; a++)
                wmma::load_matrix_sync(af[a], As + (wr * 32 + a * 16) * LDT + ks, LDT);
#pragma unroll
            for (int b = 0; b < 4; b++)
                wmma::load_matrix_sync(bf[b], Bs + ks * LDB2 + wc * 64 + b * 16, LDB2);
#pragma unroll
            for (int a = 0; a < 2; a++)
#pragma unroll
                for (int b = 0; b < 4; b++)
                    wmma::mma_sync(acc[a][b], af[a], bf[b], acc[a][b]);
        }
        __syncthreads();
    }

    float* Ob = O + ((size_t)batch * SD + it * BM) * SD + jh * BN;
#pragma unroll
    for (int a = 0; a < 2; a++)
#pragma unroll
        for (int b = 0; b < 4; b++)
            wmma::store_matrix_sync(Ob + (size_t)(wr * 32 + a * 16) * SD + wc * 64 + b * 16,
                                    acc[a][b], SD, wmma::mem_row_major);
}

// ---------------------------------------------------------------------------
extern "C" void kernel_launch(void* const* d_in, const int* in_sizes, int n_in,
                              void* d_out, int out_size)
{
    (void)in_sizes; (void)n_in; (void)out_size;
    const float* Q = (const float*)d_in[1];
    const float* K = (const float*)d_in[2];
    const float* V = (const float*)d_in[3];
    float* out = (float*)d_out;

    cudaFuncSetAttribute(k1_qk, cudaFuncAttributeMaxDynamicSharedMemorySize, K1_SMEM);
    cudaFuncSetAttribute(k2_pv, cudaFuncAttributeMaxDynamicSharedMemorySize, K2_SMEM);

    dim3 g(8, NB);
    k1_qk<<<g, 512, K1_SMEM>>>(Q, K);
    k_zred<<<NB, 512>>>();
    k2_pv<<<g, 512, K2_SMEM>>>(V, out);
}